// round 4
// baseline (speedup 1.0000x reference)
#include <cuda_runtime.h>
#include <cuda_bf16.h>
#include <math.h>

#define NMAX 200000
#define EMAX 600000
#define BMAX 10000
#define D 128

// ---------------- scratch ----------------
__device__ float g_xh[NMAX * D];
__device__ float g_xt[NMAX * D];
__device__ float g_tmp[NMAX * D];
__device__ float g_acc[NMAX * D];
__device__ float g_alS[NMAX * 2];
__device__ float g_alD[NMAX * 2];
__device__ float g_s[NMAX * 2];
__device__ float g_vdst[D];
__device__ float g_sB[BMAX];

// ---------------- helpers ----------------
__device__ __forceinline__ float lrelu(float x) { return x > 0.f ? x : 0.2f * x; }

__device__ __forceinline__ float warp_sum(float v) {
#pragma unroll
    for (int o = 16; o > 0; o >>= 1) v += __shfl_xor_sync(0xffffffffu, v, o);
    return v;
}

__device__ __forceinline__ void mma_bf16(float* c, const unsigned* a, const unsigned* b) {
    asm volatile(
        "mma.sync.aligned.m16n8k16.row.col.f32.bf16.bf16.f32 "
        "{%0,%1,%2,%3}, {%4,%5,%6,%7}, {%8,%9}, {%0,%1,%2,%3};"
        : "+f"(c[0]), "+f"(c[1]), "+f"(c[2]), "+f"(c[3])
        : "r"(a[0]), "r"(a[1]), "r"(a[2]), "r"(a[3]), "r"(b[0]), "r"(b[1]));
}

__device__ __forceinline__ void redAdd4(float* p, float x, float y, float z, float w) {
    asm volatile("red.global.add.v4.f32 [%0], {%1,%2,%3,%4};"
                 :: "l"(p), "f"(x), "f"(y), "f"(z), "f"(w) : "memory");
}

__device__ __forceinline__ void split1(float a, unsigned short& h, unsigned short& l) {
    __nv_bfloat16 ah = __float2bfloat16(a);
    h = __bfloat16_as_ushort(ah);
    l = __bfloat16_as_ushort(__float2bfloat16(a - __bfloat162float(ah)));
}

__device__ __forceinline__ void split2(float a, float b, unsigned& hi, unsigned& lo) {
    unsigned short ha, la, hb, lb;
    split1(a, ha, la);
    split1(b, hb, lb);
    hi = (unsigned)ha | ((unsigned)hb << 16);
    lo = (unsigned)la | ((unsigned)lb << 16);
}

// ---------------- bf16x3 GEMM: C[n x 128] = [A0 | A1][n x K] @ W[K x 128] + bias ----
// K=256 uses A0 for k<128 and A1 for k>=128 (both row-stride 128).
template <int K>
__global__ void __launch_bounds__(256, 2)
gemm_bf3(const float* __restrict__ A0, const float* __restrict__ A1,
         const float* __restrict__ W, const float* __restrict__ bias,
         float* __restrict__ C, int n) {
    // ushort layouts, k-contiguous, row stride 40 (pad 8): conflict-free frag loads
    __shared__ unsigned short sAh[128 * 40], sAl[128 * 40];
    __shared__ unsigned short sBh[128 * 40], sBl[128 * 40];   // [n][k] transposed
    const int row0 = blockIdx.x * 128;
    const int tid = threadIdx.x;
    const int warp = tid >> 5, lane = tid & 31;
    const int wm = warp >> 1, wn = warp & 1;
    const int g = lane >> 2, tig = lane & 3;

    float acc[2][8][4];
#pragma unroll
    for (int mt = 0; mt < 2; mt++)
#pragma unroll
        for (int nt = 0; nt < 8; nt++)
#pragma unroll
            for (int v = 0; v < 4; v++) acc[mt][nt][v] = 0.f;

    for (int k0 = 0; k0 < K; k0 += 32) {
        const float* Abase;
        int kloc, stride;
        if (K == 256) { Abase = (k0 < 128) ? A0 : A1; kloc = k0 & 127; stride = 128; }
        else          { Abase = A0; kloc = k0; stride = K; }
        // A tile 128x32 -> split bf16 hi/lo
#pragma unroll
        for (int i = 0; i < 4; i++) {
            int L = i * 256 + tid;
            int r = L >> 3, kc = (L & 7) << 2;
            float4 v = make_float4(0.f, 0.f, 0.f, 0.f);
            int gr = row0 + r;
            if (gr < n) v = *reinterpret_cast<const float4*>(Abase + (size_t)gr * stride + kloc + kc);
            unsigned h01, l01, h23, l23;
            split2(v.x, v.y, h01, l01);
            split2(v.z, v.w, h23, l23);
            unsigned* pH = reinterpret_cast<unsigned*>(sAh + r * 40 + kc);
            unsigned* pL = reinterpret_cast<unsigned*>(sAl + r * 40 + kc);
            pH[0] = h01; pH[1] = h23;
            pL[0] = l01; pL[1] = l23;
        }
        // W tile 32x128 -> transpose into [n][k], split bf16
#pragma unroll
        for (int i = 0; i < 4; i++) {
            int L = i * 256 + tid;
            int r = L >> 5;             // k row within tile
            int cc = (L & 31) << 2;     // output col
            float4 v = *reinterpret_cast<const float4*>(W + (size_t)(k0 + r) * D + cc);
            unsigned short h, l;
            split1(v.x, h, l); sBh[(cc + 0) * 40 + r] = h; sBl[(cc + 0) * 40 + r] = l;
            split1(v.y, h, l); sBh[(cc + 1) * 40 + r] = h; sBl[(cc + 1) * 40 + r] = l;
            split1(v.z, h, l); sBh[(cc + 2) * 40 + r] = h; sBl[(cc + 2) * 40 + r] = l;
            split1(v.w, h, l); sBh[(cc + 3) * 40 + r] = h; sBl[(cc + 3) * 40 + r] = l;
        }
        __syncthreads();
#pragma unroll
        for (int kk = 0; kk < 32; kk += 16) {
            unsigned ah[2][4], al[2][4];
#pragma unroll
            for (int mt = 0; mt < 2; mt++) {
                int base = (wm * 32 + mt * 16 + g) * 40 + kk + 2 * tig;
                ah[mt][0] = *reinterpret_cast<unsigned*>(sAh + base);
                ah[mt][1] = *reinterpret_cast<unsigned*>(sAh + base + 8 * 40);
                ah[mt][2] = *reinterpret_cast<unsigned*>(sAh + base + 8);
                ah[mt][3] = *reinterpret_cast<unsigned*>(sAh + base + 8 * 40 + 8);
                al[mt][0] = *reinterpret_cast<unsigned*>(sAl + base);
                al[mt][1] = *reinterpret_cast<unsigned*>(sAl + base + 8 * 40);
                al[mt][2] = *reinterpret_cast<unsigned*>(sAl + base + 8);
                al[mt][3] = *reinterpret_cast<unsigned*>(sAl + base + 8 * 40 + 8);
            }
#pragma unroll
            for (int h2 = 0; h2 < 2; h2++) {
                unsigned bh[4][2], bl[4][2];
#pragma unroll
                for (int nt = 0; nt < 4; nt++) {
                    int cb = wn * 64 + (h2 * 4 + nt) * 8 + g;
                    int bbase = cb * 40 + kk + 2 * tig;
                    bh[nt][0] = *reinterpret_cast<unsigned*>(sBh + bbase);
                    bh[nt][1] = *reinterpret_cast<unsigned*>(sBh + bbase + 8);
                    bl[nt][0] = *reinterpret_cast<unsigned*>(sBl + bbase);
                    bl[nt][1] = *reinterpret_cast<unsigned*>(sBl + bbase + 8);
                }
#pragma unroll
                for (int mt = 0; mt < 2; mt++)
#pragma unroll
                    for (int nt = 0; nt < 4; nt++) {
                        float* c = acc[mt][h2 * 4 + nt];
                        mma_bf16(c, al[mt], bh[nt]);
                        mma_bf16(c, ah[mt], bl[nt]);
                        mma_bf16(c, ah[mt], bh[nt]);
                    }
            }
        }
        __syncthreads();
    }

#pragma unroll
    for (int mt = 0; mt < 2; mt++) {
        int r0 = row0 + wm * 32 + mt * 16 + g;
        int r1 = r0 + 8;
#pragma unroll
        for (int nt = 0; nt < 8; nt++) {
            int c = wn * 64 + nt * 8 + 2 * tig;
            float b0 = 0.f, b1 = 0.f;
            if (bias) { b0 = __ldg(bias + c); b1 = __ldg(bias + c + 1); }
            if (r0 < n) {
                float* cp = C + (size_t)r0 * D + c;
                cp[0] = acc[mt][nt][0] + b0;
                cp[1] = acc[mt][nt][1] + b1;
            }
            if (r1 < n) {
                float* cp = C + (size_t)r1 * D + c;
                cp[0] = acc[mt][nt][2] + b0;
                cp[1] = acc[mt][nt][3] + b1;
            }
        }
    }
}

// ---------------- node prep, 2-head ----------------
__global__ void node_prep2(const float* __restrict__ xs,
                           const float* __restrict__ a_src, const float* __restrict__ a_dst,
                           float* alS, float* alD, float* s, int n) {
    int warp = (blockIdx.x * blockDim.x + threadIdx.x) >> 5;
    int lane = threadIdx.x & 31;
    if (warp >= n) return;
    int c = lane * 4;
    float4 x  = *reinterpret_cast<const float4*>(xs + (size_t)warp * D + c);
    float4 as = *reinterpret_cast<const float4*>(a_src + c);
    float4 ad = *reinterpret_cast<const float4*>(a_dst + c);
    float ps = x.x * as.x + x.y * as.y + x.z * as.z + x.w * as.w;
    float pd = x.x * ad.x + x.y * ad.y + x.z * ad.z + x.w * ad.w;
#pragma unroll
    for (int o = 8; o > 0; o >>= 1) {
        ps += __shfl_down_sync(0xffffffffu, ps, o, 16);
        pd += __shfl_down_sync(0xffffffffu, pd, o, 16);
    }
    if ((lane & 15) == 0) {
        int h = lane >> 4;
        alS[warp * 2 + h] = ps;
        alD[warp * 2 + h] = pd;
        s[warp * 2 + h] = 0.f;
    }
}

// ---------------- node prep, 1-head ----------------
__global__ void node_prep1(const float* __restrict__ xsS, const float* __restrict__ vS,
                           const float* __restrict__ xsD, const float* __restrict__ vD,
                           float* alS, float* alD, float* s, int n) {
    int warp = (blockIdx.x * blockDim.x + threadIdx.x) >> 5;
    int lane = threadIdx.x & 31;
    if (warp >= n) return;
    int c = lane * 4;
    float4 xa = *reinterpret_cast<const float4*>(xsS + (size_t)warp * D + c);
    float4 va = *reinterpret_cast<const float4*>(vS + c);
    float4 xb = *reinterpret_cast<const float4*>(xsD + (size_t)warp * D + c);
    float4 vb = *reinterpret_cast<const float4*>(vD + c);
    float ps = xa.x * va.x + xa.y * va.y + xa.z * va.z + xa.w * va.w;
    float pd = xb.x * vb.x + xb.y * vb.y + xb.z * vb.z + xb.w * vb.w;
    ps = warp_sum(ps);
    pd = warp_sum(pd);
    if (lane == 0) {
        alS[warp] = ps;
        alD[warp] = pd;
        s[warp] = 0.f;
    }
}

// ---------------- edge aggregate (no max pass) ----------------
__global__ void edge_agg2(const int* __restrict__ src, const int* __restrict__ dst,
                          const float* __restrict__ alS, const float* __restrict__ alD,
                          float* s, const float* __restrict__ xs, float* acc, int E) {
    int warp = (blockIdx.x * blockDim.x + threadIdx.x) >> 5;
    int lane = threadIdx.x & 31;
    if (warp >= E) return;
    int u = src[warp], v = dst[warp];
    int h = lane >> 4;
    float w = 0.f;
    if ((lane & 15) == 0) {
        float e = lrelu(alS[u * 2 + h] + alD[v * 2 + h]);
        w = __expf(e);
        atomicAdd(&s[v * 2 + h], w);
    }
    w = __shfl_sync(0xffffffffu, w, lane & 16);
    int c = lane * 4;
    float4 x = *reinterpret_cast<const float4*>(xs + (size_t)u * D + c);
    redAdd4(acc + (size_t)v * D + c, w * x.x, w * x.y, w * x.z, w * x.w);
}

__global__ void edge_agg1(const int* __restrict__ src, const int* __restrict__ dst,
                          const float* __restrict__ alS, const float* __restrict__ alD,
                          float* s, const float* __restrict__ xs, float* acc, int E) {
    int warp = (blockIdx.x * blockDim.x + threadIdx.x) >> 5;
    int lane = threadIdx.x & 31;
    if (warp >= E) return;
    int u = src[warp], v = dst[warp];
    float w = 0.f;
    if (lane == 0) {
        float e = lrelu(alS[u] + alD[v]);
        w = __expf(e);
        atomicAdd(&s[v], w);
    }
    w = __shfl_sync(0xffffffffu, w, 0);
    int c = lane * 4;
    float4 x = *reinterpret_cast<const float4*>(xs + (size_t)u * D + c);
    redAdd4(acc + (size_t)v * D + c, w * x.x, w * x.y, w * x.z, w * x.w);
}

// ---------------- finalize stage 1 ----------------
__global__ void fin_stage1(const float* __restrict__ acc, const float* __restrict__ xs,
                           const float* __restrict__ alS, const float* __restrict__ alD,
                           const float* __restrict__ s,
                           const float* __restrict__ bgat, const float* __restrict__ g,
                           const float* __restrict__ bb, float* __restrict__ out, int n) {
    int warp = (blockIdx.x * blockDim.x + threadIdx.x) >> 5;
    int lane = threadIdx.x & 31;
    if (warp >= n) return;
    int h = lane >> 4;
    int c = lane * 4;
    float e  = lrelu(alS[warp * 2 + h] + alD[warp * 2 + h]);
    float ws = __expf(e);
    float inv = 1.f / (s[warp * 2 + h] + ws + 1e-16f);
    float4 A = *reinterpret_cast<const float4*>(acc + (size_t)warp * D + c);
    float4 X = *reinterpret_cast<const float4*>(xs + (size_t)warp * D + c);
    float4 Bt = *reinterpret_cast<const float4*>(bgat + c);
    float4 val;
    val.x = (A.x + ws * X.x) * inv + Bt.x;
    val.y = (A.y + ws * X.y) * inv + Bt.y;
    val.z = (A.z + ws * X.z) * inv + Bt.z;
    val.w = (A.w + ws * X.w) * inv + Bt.w;
    float sum = warp_sum(val.x + val.y + val.z + val.w);
    float sq  = warp_sum(val.x * val.x + val.y * val.y + val.z * val.z + val.w * val.w);
    float mu = sum * (1.f / 128.f);
    float var = sq * (1.f / 128.f) - mu * mu;
    float r = rsqrtf(var + 1e-5f);
    float4 gg = *reinterpret_cast<const float4*>(g + c);
    float4 bv = *reinterpret_cast<const float4*>(bb + c);
    float4 y;
    y.x = (val.x - mu) * r * gg.x + bv.x;
    y.y = (val.y - mu) * r * gg.y + bv.y;
    y.z = (val.z - mu) * r * gg.z + bv.z;
    y.w = (val.w - mu) * r * gg.w + bv.w;
    y.x = y.x > 0.f ? y.x : expm1f(y.x);
    y.y = y.y > 0.f ? y.y : expm1f(y.y);
    y.z = y.z > 0.f ? y.z : expm1f(y.z);
    y.w = y.w > 0.f ? y.w : expm1f(y.w);
    *reinterpret_cast<float4*>(out + (size_t)warp * D + c) = y;
}

// ---------------- finalize 1-head GAT in place ----------------
__global__ void fin1(float* __restrict__ out, const float* __restrict__ xs,
                     const float* __restrict__ alS, const float* __restrict__ alD,
                     const float* __restrict__ s,
                     const float* __restrict__ bias, int selfloop, int n) {
    int warp = (blockIdx.x * blockDim.x + threadIdx.x) >> 5;
    int lane = threadIdx.x & 31;
    if (warp >= n) return;
    int c = lane * 4;
    float ws = 0.f, inv;
    if (selfloop) {
        ws = __expf(lrelu(alS[warp] + alD[warp]));
        inv = 1.f / (s[warp] + ws + 1e-16f);
    } else {
        inv = 1.f / (s[warp] + 1e-16f);
    }
    float4 A = *reinterpret_cast<const float4*>(out + (size_t)warp * D + c);
    float4 X = *reinterpret_cast<const float4*>(xs + (size_t)warp * D + c);
    float4 Bv = *reinterpret_cast<const float4*>(bias + c);
    float4 y;
    y.x = (A.x + ws * X.x) * inv + Bv.x;
    y.y = (A.y + ws * X.y) * inv + Bv.y;
    y.z = (A.z + ws * X.z) * inv + Bv.z;
    y.w = (A.w + ws * X.w) * inv + Bv.w;
    *reinterpret_cast<float4*>(out + (size_t)warp * D + c) = y;
}

// ---------------- misc ----------------
__global__ void compute_vdst(const float* __restrict__ Wd, const float* __restrict__ ad,
                             float* v) {
    int i = threadIdx.x;
    float sum = 0.f;
    for (int j = 0; j < D; j++) sum += Wd[i * D + j] * ad[j];
    v[i] = sum;
}

// ---------------- SAG readout (linearized) ----------------
__global__ void sag_prep(const float* __restrict__ x, const float* __restrict__ w_rel,
                         const float* __restrict__ w_root, const float* __restrict__ b_rel,
                         float* pRel, float* attn, int n) {
    int warp = (blockIdx.x * blockDim.x + threadIdx.x) >> 5;
    int lane = threadIdx.x & 31;
    if (warp >= n) return;
    int c = lane * 4;
    float4 xv = *reinterpret_cast<const float4*>(x + (size_t)warp * D + c);
    float4 wr = *reinterpret_cast<const float4*>(w_rel + c);
    float4 wo = *reinterpret_cast<const float4*>(w_root + c);
    float pr = xv.x * wr.x + xv.y * wr.y + xv.z * wr.z + xv.w * wr.w;
    float po = xv.x * wo.x + xv.y * wo.y + xv.z * wo.z + xv.w * wo.w;
    pr = warp_sum(pr);
    po = warp_sum(po);
    if (lane == 0) {
        pRel[warp] = pr;
        attn[warp] = po + __ldg(b_rel);
    }
}

__global__ void sag_edge(const int* __restrict__ src, const int* __restrict__ dst,
                         const float* __restrict__ pRel, float* attn, int E) {
    int e = blockIdx.x * blockDim.x + threadIdx.x;
    if (e >= E) return;
    atomicAdd(&attn[dst[e]], pRel[src[e]]);
}

__global__ void batch_expsum(float* attn, const int* __restrict__ batch,
                             float* sB, int n) {
    int i = blockIdx.x * blockDim.x + threadIdx.x;
    if (i >= n) return;
    float w = __expf(attn[i]);
    attn[i] = w;
    atomicAdd(&sB[batch[i]], w);
}

__global__ void emb_agg(const float* __restrict__ x, const float* __restrict__ attn,
                        const int* __restrict__ batch, const float* __restrict__ sB,
                        float* emb, int n) {
    int warp = (blockIdx.x * blockDim.x + threadIdx.x) >> 5;
    int lane = threadIdx.x & 31;
    if (warp >= n) return;
    int g = batch[warp];
    float coef = attn[warp] / (sB[g] + 1e-16f);
    int c = lane * 4;
    float4 xv = *reinterpret_cast<const float4*>(x + (size_t)warp * D + c);
    redAdd4(emb + (size_t)g * D + c, coef * xv.x, coef * xv.y, coef * xv.z, coef * xv.w);
}

// ---------------- host orchestration ----------------
extern "C" void kernel_launch(void* const* d_in, const int* in_sizes, int n_in,
                              void* d_out, int out_size) {
    const float* h_x        = (const float*)d_in[0];
    const float* t_x        = (const float*)d_in[1];
    const float* W_gat      = (const float*)d_in[2];
    const float* a_src_gat  = (const float*)d_in[3];
    const float* a_dst_gat  = (const float*)d_in[4];
    const float* b_gat      = (const float*)d_in[5];
    const float* ln_g       = (const float*)d_in[6];
    const float* ln_b       = (const float*)d_in[7];
    const float* W_intra    = (const float*)d_in[8];
    const float* a_src_in   = (const float*)d_in[9];
    const float* a_dst_in   = (const float*)d_in[10];
    const float* b_intra    = (const float*)d_in[11];
    const float* W_int_src  = (const float*)d_in[12];
    const float* W_int_dst  = (const float*)d_in[13];
    const float* a_src_it   = (const float*)d_in[14];
    const float* a_dst_it   = (const float*)d_in[15];
    const float* b_inter    = (const float*)d_in[16];
    const float* W_reduce   = (const float*)d_in[17];
    const float* b_reduce   = (const float*)d_in[18];
    const float* w_rel      = (const float*)d_in[19];
    const float* b_rel      = (const float*)d_in[20];
    const float* w_root     = (const float*)d_in[21];
    const int*   h_ei       = (const int*)d_in[22];
    const int*   t_ei       = (const int*)d_in[23];
    const int*   b_ei       = (const int*)d_in[24];
    const int*   h_batch    = (const int*)d_in[25];
    const int*   t_batch    = (const int*)d_in[26];
    (void)n_in;

    const int N = in_sizes[0] / 64;
    const int E = in_sizes[22] / 2;
    const long long B = ((long long)out_size - 6LL * N * D) / (2 * D);

    float* out = (float*)d_out;
    const size_t NT = (size_t)N * D, BT = (size_t)B * D;
    float* h_fused = out;
    float* t_fused = out + NT;
    float* h_emb   = out + 2 * NT;
    float* t_emb   = h_emb + BT;
    float* h_intra = t_emb + BT;
    float* t_intra = h_intra + NT;
    float* h_inter = t_intra + NT;
    float* t_inter = h_inter + NT;

    float *xh, *xt, *tmp, *acc, *alS, *alD, *s, *vdst, *sB;
    cudaGetSymbolAddress((void**)&xh,   g_xh);
    cudaGetSymbolAddress((void**)&xt,   g_xt);
    cudaGetSymbolAddress((void**)&tmp,  g_tmp);
    cudaGetSymbolAddress((void**)&acc,  g_acc);
    cudaGetSymbolAddress((void**)&alS,  g_alS);
    cudaGetSymbolAddress((void**)&alD,  g_alD);
    cudaGetSymbolAddress((void**)&s,    g_s);
    cudaGetSymbolAddress((void**)&vdst, g_vdst);
    cudaGetSymbolAddress((void**)&sB,   g_sB);

    const int TB = 256;
    const int nbNodeW = (N + 7) / 8;
    const int nbEdgeW = (E + 7) / 8;
    const int nbNodeT = (N + TB - 1) / TB;
    const int nbEdgeT = (E + TB - 1) / TB;
    const int nbGemm  = (N + 127) / 128;

    const int* h_src = h_ei;       const int* h_dst = h_ei + E;
    const int* t_src = t_ei;       const int* t_dst = t_ei + E;
    const int* b_src = b_ei;       const int* b_dst = b_ei + E;

    // ===== Stage 1: feature GAT + LN + ELU =====
    {
        const float* xin[2] = { h_x, t_x };
        const int* esrc[2]  = { h_src, t_src };
        const int* edst[2]  = { h_dst, t_dst };
        float* xout[2]      = { xh, xt };
        for (int g2 = 0; g2 < 2; g2++) {
            gemm_bf3<64><<<nbGemm, TB>>>(xin[g2], nullptr, W_gat, nullptr, tmp, N);
            cudaMemsetAsync(acc, 0, NT * sizeof(float));
            node_prep2<<<nbNodeW, TB>>>(tmp, a_src_gat, a_dst_gat, alS, alD, s, N);
            edge_agg2<<<nbEdgeW, TB>>>(esrc[g2], edst[g2], alS, alD, s, tmp, acc, E);
            fin_stage1<<<nbNodeW, TB>>>(acc, tmp, alS, alD, s, b_gat, ln_g, ln_b, xout[g2], N);
        }
    }

    // ===== Stage 2: intra GAT =====
    {
        const float* xin[2] = { xh, xt };
        const int* esrc[2]  = { h_src, t_src };
        const int* edst[2]  = { h_dst, t_dst };
        float* oreg[2]      = { h_intra, t_intra };
        for (int g2 = 0; g2 < 2; g2++) {
            gemm_bf3<128><<<nbGemm, TB>>>(xin[g2], nullptr, W_intra, nullptr, tmp, N);
            cudaMemsetAsync(oreg[g2], 0, NT * sizeof(float));
            node_prep1<<<nbNodeW, TB>>>(tmp, a_src_in, tmp, a_dst_in, alS, alD, s, N);
            edge_agg1<<<nbEdgeW, TB>>>(esrc[g2], edst[g2], alS, alD, s, tmp, oreg[g2], E);
            fin1<<<nbNodeW, TB>>>(oreg[g2], tmp, alS, alD, s, b_intra, 1, N);
        }
    }

    // ===== Stage 3: inter (bipartite) GAT =====
    compute_vdst<<<1, 128>>>(W_int_dst, a_dst_it, vdst);
    {
        gemm_bf3<128><<<nbGemm, TB>>>(xh, nullptr, W_int_src, nullptr, tmp, N);
        cudaMemsetAsync(t_inter, 0, NT * sizeof(float));
        node_prep1<<<nbNodeW, TB>>>(tmp, a_src_it, xt, vdst, alS, alD, s, N);
        edge_agg1<<<nbEdgeW, TB>>>(b_src, b_dst, alS, alD, s, tmp, t_inter, E);
        fin1<<<nbNodeW, TB>>>(t_inter, tmp, alS, alD, s, b_inter, 0, N);
    }
    {
        gemm_bf3<128><<<nbGemm, TB>>>(xt, nullptr, W_int_src, nullptr, tmp, N);
        cudaMemsetAsync(h_inter, 0, NT * sizeof(float));
        node_prep1<<<nbNodeW, TB>>>(tmp, a_src_it, xh, vdst, alS, alD, s, N);
        edge_agg1<<<nbEdgeW, TB>>>(b_dst, b_src, alS, alD, s, tmp, h_inter, E);
        fin1<<<nbNodeW, TB>>>(h_inter, tmp, alS, alD, s, b_inter, 0, N);
    }

    // ===== Stage 4: fused = [intra | inter] @ W_reduce + b_reduce (K=256 fused) =====
    gemm_bf3<256><<<nbGemm, TB>>>(h_intra, h_inter, W_reduce, b_reduce, h_fused, N);
    gemm_bf3<256><<<nbGemm, TB>>>(t_intra, t_inter, W_reduce, b_reduce, t_fused, N);

    // ===== Stage 5: SAG readout (linearized) =====
    {
        const float* x[2]   = { h_fused, t_fused };
        const int* esrc[2]  = { h_src, t_src };
        const int* edst[2]  = { h_dst, t_dst };
        const int* batch[2] = { h_batch, t_batch };
        float* emb[2]       = { h_emb, t_emb };
        for (int g2 = 0; g2 < 2; g2++) {
            sag_prep<<<nbNodeW, TB>>>(x[g2], w_rel, w_root, b_rel, alS, alD, N);
            sag_edge<<<nbEdgeT, TB>>>(esrc[g2], edst[g2], alS, alD, E);
            cudaMemsetAsync(sB, 0, B * sizeof(float));
            batch_expsum<<<nbNodeT, TB>>>(alD, batch[g2], sB, N);
            cudaMemsetAsync(emb[g2], 0, BT * sizeof(float));
            emb_agg<<<nbNodeW, TB>>>(x[g2], alD, batch[g2], sB, emb[g2], N);
        }
    }
}

// round 5
// speedup vs baseline: 1.3299x; 1.3299x over previous
#include <cuda_runtime.h>
#include <cuda_bf16.h>
#include <math.h>

#define NMAX 200000
#define EMAX 600000
#define BMAX 10000
#define D 128

// ---------------- scratch ----------------
__device__ float g_xh[NMAX * D];
__device__ float g_xt[NMAX * D];
__device__ float g_tmp[NMAX * D];
__device__ float g_acc[NMAX * D];
__device__ float g_alS[NMAX * 2];
__device__ float g_alD[NMAX * 2];
__device__ float g_s[NMAX * 2];
__device__ float g_vdst[D];
__device__ float g_sB[BMAX];

// ---------------- helpers ----------------
__device__ __forceinline__ float lrelu(float x) { return x > 0.f ? x : 0.2f * x; }

__device__ __forceinline__ float warp_sum(float v) {
#pragma unroll
    for (int o = 16; o > 0; o >>= 1) v += __shfl_xor_sync(0xffffffffu, v, o);
    return v;
}

__device__ __forceinline__ void mma_bf16(float* c, const unsigned* a, const unsigned* b) {
    asm volatile(
        "mma.sync.aligned.m16n8k16.row.col.f32.bf16.bf16.f32 "
        "{%0,%1,%2,%3}, {%4,%5,%6,%7}, {%8,%9}, {%0,%1,%2,%3};"
        : "+f"(c[0]), "+f"(c[1]), "+f"(c[2]), "+f"(c[3])
        : "r"(a[0]), "r"(a[1]), "r"(a[2]), "r"(a[3]), "r"(b[0]), "r"(b[1]));
}

__device__ __forceinline__ void ldsm4(unsigned* r, const void* p) {
    unsigned addr = (unsigned)__cvta_generic_to_shared(p);
    asm volatile("ldmatrix.sync.aligned.m8n8.x4.shared.b16 {%0,%1,%2,%3}, [%4];"
                 : "=r"(r[0]), "=r"(r[1]), "=r"(r[2]), "=r"(r[3]) : "r"(addr));
}

__device__ __forceinline__ void ldsm4t(unsigned* r, const void* p) {
    unsigned addr = (unsigned)__cvta_generic_to_shared(p);
    asm volatile("ldmatrix.sync.aligned.m8n8.x4.trans.shared.b16 {%0,%1,%2,%3}, [%4];"
                 : "=r"(r[0]), "=r"(r[1]), "=r"(r[2]), "=r"(r[3]) : "r"(addr));
}

__device__ __forceinline__ void redAdd4(float* p, float x, float y, float z, float w) {
    asm volatile("red.global.add.v4.f32 [%0], {%1,%2,%3,%4};"
                 :: "l"(p), "f"(x), "f"(y), "f"(z), "f"(w) : "memory");
}

__device__ __forceinline__ void split1(float a, unsigned short& h, unsigned short& l) {
    __nv_bfloat16 ah = __float2bfloat16(a);
    h = __bfloat16_as_ushort(ah);
    l = __bfloat16_as_ushort(__float2bfloat16(a - __bfloat162float(ah)));
}

__device__ __forceinline__ void split2(float a, float b, unsigned& hi, unsigned& lo) {
    unsigned short ha, la, hb, lb;
    split1(a, ha, la);
    split1(b, hb, lb);
    hi = (unsigned)ha | ((unsigned)hb << 16);
    lo = (unsigned)la | ((unsigned)lb << 16);
}

// ---------------- bf16x3 GEMM (ldmatrix path) ----------------
// C[n x 128] = [A0 | A1][n x K] @ W[K x 128] + bias.  K=256: A0 k<128, A1 k>=128.
template <int K>
__global__ void __launch_bounds__(256, 2)
gemm_bf3(const float* __restrict__ A0, const float* __restrict__ A1,
         const float* __restrict__ W, const float* __restrict__ bias,
         float* __restrict__ C, int n) {
    __shared__ __align__(16) unsigned short sAh[128][40], sAl[128][40];  // [m][k], pad 8
    __shared__ __align__(16) unsigned short sBh[32][136], sBl[32][136];  // [k][n], pad 8
    const int row0 = blockIdx.x * 128;
    const int tid = threadIdx.x;
    const int warp = tid >> 5, lane = tid & 31;
    const int wm = warp >> 1, wn = warp & 1;
    const int g = lane >> 2, tig = lane & 3;
    const int l15 = lane & 15, l16o = ((lane >> 4) & 1) * 8;

    float acc[2][8][4];
#pragma unroll
    for (int mt = 0; mt < 2; mt++)
#pragma unroll
        for (int nt = 0; nt < 8; nt++)
#pragma unroll
            for (int v = 0; v < 4; v++) acc[mt][nt][v] = 0.f;

    for (int k0 = 0; k0 < K; k0 += 32) {
        const float* Abase;
        int kloc, stride;
        if (K == 256) { Abase = (k0 < 128) ? A0 : A1; kloc = k0 & 127; stride = 128; }
        else          { Abase = A0; kloc = k0; stride = K; }
        // ---- A tile 128x32 -> hi/lo packed bf16, [m][k] ----
#pragma unroll
        for (int i = 0; i < 4; i++) {
            int L = i * 256 + tid;
            int r = L >> 3, kc = (L & 7) << 2;
            float4 v = make_float4(0.f, 0.f, 0.f, 0.f);
            int gr = row0 + r;
            if (gr < n) v = *reinterpret_cast<const float4*>(Abase + (size_t)gr * stride + kloc + kc);
            unsigned h01, l01, h23, l23;
            split2(v.x, v.y, h01, l01);
            split2(v.z, v.w, h23, l23);
            *reinterpret_cast<uint2*>(&sAh[r][kc]) = make_uint2(h01, h23);
            *reinterpret_cast<uint2*>(&sAl[r][kc]) = make_uint2(l01, l23);
        }
        // ---- W tile 32x128 -> hi/lo packed bf16, natural [k][n] ----
#pragma unroll
        for (int i = 0; i < 4; i++) {
            int L = i * 256 + tid;
            int r = L >> 5, cc = (L & 31) << 2;
            float4 v = *reinterpret_cast<const float4*>(W + (size_t)(k0 + r) * D + cc);
            unsigned h01, l01, h23, l23;
            split2(v.x, v.y, h01, l01);
            split2(v.z, v.w, h23, l23);
            *reinterpret_cast<uint2*>(&sBh[r][cc]) = make_uint2(h01, h23);
            *reinterpret_cast<uint2*>(&sBl[r][cc]) = make_uint2(l01, l23);
        }
        __syncthreads();
#pragma unroll
        for (int kk = 0; kk < 32; kk += 16) {
            unsigned ah[2][4], al[2][4];
#pragma unroll
            for (int mt = 0; mt < 2; mt++) {
                int ar = wm * 32 + mt * 16 + l15;
                ldsm4(ah[mt], &sAh[ar][kk + l16o]);
                ldsm4(al[mt], &sAl[ar][kk + l16o]);
            }
            int br = kk + l15;
#pragma unroll
            for (int h2 = 0; h2 < 2; h2++) {
                unsigned bh[4][2], bl[4][2], t4[4];
#pragma unroll
                for (int p = 0; p < 2; p++) {
                    int bc = wn * 64 + h2 * 32 + p * 16 + l16o;
                    ldsm4t(t4, &sBh[br][bc]);
                    bh[2 * p][0] = t4[0]; bh[2 * p][1] = t4[1];
                    bh[2 * p + 1][0] = t4[2]; bh[2 * p + 1][1] = t4[3];
                    ldsm4t(t4, &sBl[br][bc]);
                    bl[2 * p][0] = t4[0]; bl[2 * p][1] = t4[1];
                    bl[2 * p + 1][0] = t4[2]; bl[2 * p + 1][1] = t4[3];
                }
#pragma unroll
                for (int mt = 0; mt < 2; mt++)
#pragma unroll
                    for (int nt = 0; nt < 4; nt++) {
                        float* c = acc[mt][h2 * 4 + nt];
                        mma_bf16(c, al[mt], bh[nt]);
                        mma_bf16(c, ah[mt], bl[nt]);
                        mma_bf16(c, ah[mt], bh[nt]);
                    }
            }
        }
        __syncthreads();
    }

#pragma unroll
    for (int mt = 0; mt < 2; mt++) {
        int r0 = row0 + wm * 32 + mt * 16 + g;
        int r1 = r0 + 8;
#pragma unroll
        for (int nt = 0; nt < 8; nt++) {
            int c = wn * 64 + nt * 8 + 2 * tig;
            float b0 = 0.f, b1 = 0.f;
            if (bias) { b0 = __ldg(bias + c); b1 = __ldg(bias + c + 1); }
            if (r0 < n) {
                float* cp = C + (size_t)r0 * D + c;
                cp[0] = acc[mt][nt][0] + b0;
                cp[1] = acc[mt][nt][1] + b1;
            }
            if (r1 < n) {
                float* cp = C + (size_t)r1 * D + c;
                cp[0] = acc[mt][nt][2] + b0;
                cp[1] = acc[mt][nt][3] + b1;
            }
        }
    }
}

// ---------------- node prep, 2-head ----------------
__global__ void node_prep2(const float* __restrict__ xs,
                           const float* __restrict__ a_src, const float* __restrict__ a_dst,
                           float* alS, float* alD, float* s, int n) {
    int warp = (blockIdx.x * blockDim.x + threadIdx.x) >> 5;
    int lane = threadIdx.x & 31;
    if (warp >= n) return;
    int c = lane * 4;
    float4 x  = *reinterpret_cast<const float4*>(xs + (size_t)warp * D + c);
    float4 as = *reinterpret_cast<const float4*>(a_src + c);
    float4 ad = *reinterpret_cast<const float4*>(a_dst + c);
    float ps = x.x * as.x + x.y * as.y + x.z * as.z + x.w * as.w;
    float pd = x.x * ad.x + x.y * ad.y + x.z * ad.z + x.w * ad.w;
#pragma unroll
    for (int o = 8; o > 0; o >>= 1) {
        ps += __shfl_down_sync(0xffffffffu, ps, o, 16);
        pd += __shfl_down_sync(0xffffffffu, pd, o, 16);
    }
    if ((lane & 15) == 0) {
        int h = lane >> 4;
        alS[warp * 2 + h] = ps;
        alD[warp * 2 + h] = pd;
        s[warp * 2 + h] = 0.f;
    }
}

// ---------------- node prep, 1-head ----------------
__global__ void node_prep1(const float* __restrict__ xsS, const float* __restrict__ vS,
                           const float* __restrict__ xsD, const float* __restrict__ vD,
                           float* alS, float* alD, float* s, int n) {
    int warp = (blockIdx.x * blockDim.x + threadIdx.x) >> 5;
    int lane = threadIdx.x & 31;
    if (warp >= n) return;
    int c = lane * 4;
    float4 xa = *reinterpret_cast<const float4*>(xsS + (size_t)warp * D + c);
    float4 va = *reinterpret_cast<const float4*>(vS + c);
    float4 xb = *reinterpret_cast<const float4*>(xsD + (size_t)warp * D + c);
    float4 vb = *reinterpret_cast<const float4*>(vD + c);
    float ps = xa.x * va.x + xa.y * va.y + xa.z * va.z + xa.w * va.w;
    float pd = xb.x * vb.x + xb.y * vb.y + xb.z * vb.z + xb.w * vb.w;
    ps = warp_sum(ps);
    pd = warp_sum(pd);
    if (lane == 0) {
        alS[warp] = ps;
        alD[warp] = pd;
        s[warp] = 0.f;
    }
}

// ---------------- edge aggregate ----------------
__global__ void edge_agg2(const int* __restrict__ src, const int* __restrict__ dst,
                          const float* __restrict__ alS, const float* __restrict__ alD,
                          float* s, const float* __restrict__ xs, float* acc, int E) {
    int warp = (blockIdx.x * blockDim.x + threadIdx.x) >> 5;
    int lane = threadIdx.x & 31;
    if (warp >= E) return;
    int u = src[warp], v = dst[warp];
    int h = lane >> 4;
    float w = 0.f;
    if ((lane & 15) == 0) {
        float e = lrelu(alS[u * 2 + h] + alD[v * 2 + h]);
        w = __expf(e);
        atomicAdd(&s[v * 2 + h], w);
    }
    w = __shfl_sync(0xffffffffu, w, lane & 16);
    int c = lane * 4;
    float4 x = *reinterpret_cast<const float4*>(xs + (size_t)u * D + c);
    redAdd4(acc + (size_t)v * D + c, w * x.x, w * x.y, w * x.z, w * x.w);
}

__global__ void edge_agg1(const int* __restrict__ src, const int* __restrict__ dst,
                          const float* __restrict__ alS, const float* __restrict__ alD,
                          float* s, const float* __restrict__ xs, float* acc, int E) {
    int warp = (blockIdx.x * blockDim.x + threadIdx.x) >> 5;
    int lane = threadIdx.x & 31;
    if (warp >= E) return;
    int u = src[warp], v = dst[warp];
    float w = 0.f;
    if (lane == 0) {
        float e = lrelu(alS[u] + alD[v]);
        w = __expf(e);
        atomicAdd(&s[v], w);
    }
    w = __shfl_sync(0xffffffffu, w, 0);
    int c = lane * 4;
    float4 x = *reinterpret_cast<const float4*>(xs + (size_t)u * D + c);
    redAdd4(acc + (size_t)v * D + c, w * x.x, w * x.y, w * x.z, w * x.w);
}

// ---------------- finalize stage 1 ----------------
__global__ void fin_stage1(const float* __restrict__ acc, const float* __restrict__ xs,
                           const float* __restrict__ alS, const float* __restrict__ alD,
                           const float* __restrict__ s,
                           const float* __restrict__ bgat, const float* __restrict__ g,
                           const float* __restrict__ bb, float* __restrict__ out, int n) {
    int warp = (blockIdx.x * blockDim.x + threadIdx.x) >> 5;
    int lane = threadIdx.x & 31;
    if (warp >= n) return;
    int h = lane >> 4;
    int c = lane * 4;
    float e  = lrelu(alS[warp * 2 + h] + alD[warp * 2 + h]);
    float ws = __expf(e);
    float inv = 1.f / (s[warp * 2 + h] + ws + 1e-16f);
    float4 A = *reinterpret_cast<const float4*>(acc + (size_t)warp * D + c);
    float4 X = *reinterpret_cast<const float4*>(xs + (size_t)warp * D + c);
    float4 Bt = *reinterpret_cast<const float4*>(bgat + c);
    float4 val;
    val.x = (A.x + ws * X.x) * inv + Bt.x;
    val.y = (A.y + ws * X.y) * inv + Bt.y;
    val.z = (A.z + ws * X.z) * inv + Bt.z;
    val.w = (A.w + ws * X.w) * inv + Bt.w;
    float sum = warp_sum(val.x + val.y + val.z + val.w);
    float sq  = warp_sum(val.x * val.x + val.y * val.y + val.z * val.z + val.w * val.w);
    float mu = sum * (1.f / 128.f);
    float var = sq * (1.f / 128.f) - mu * mu;
    float r = rsqrtf(var + 1e-5f);
    float4 gg = *reinterpret_cast<const float4*>(g + c);
    float4 bv = *reinterpret_cast<const float4*>(bb + c);
    float4 y;
    y.x = (val.x - mu) * r * gg.x + bv.x;
    y.y = (val.y - mu) * r * gg.y + bv.y;
    y.z = (val.z - mu) * r * gg.z + bv.z;
    y.w = (val.w - mu) * r * gg.w + bv.w;
    y.x = y.x > 0.f ? y.x : expm1f(y.x);
    y.y = y.y > 0.f ? y.y : expm1f(y.y);
    y.z = y.z > 0.f ? y.z : expm1f(y.z);
    y.w = y.w > 0.f ? y.w : expm1f(y.w);
    *reinterpret_cast<float4*>(out + (size_t)warp * D + c) = y;
}

// ---------------- finalize 1-head GAT ----------------
__global__ void fin1(float* __restrict__ out, const float* __restrict__ xs,
                     const float* __restrict__ alS, const float* __restrict__ alD,
                     const float* __restrict__ s,
                     const float* __restrict__ bias, int selfloop, int n) {
    int warp = (blockIdx.x * blockDim.x + threadIdx.x) >> 5;
    int lane = threadIdx.x & 31;
    if (warp >= n) return;
    int c = lane * 4;
    float ws = 0.f, inv;
    if (selfloop) {
        ws = __expf(lrelu(alS[warp] + alD[warp]));
        inv = 1.f / (s[warp] + ws + 1e-16f);
    } else {
        inv = 1.f / (s[warp] + 1e-16f);
    }
    float4 A = *reinterpret_cast<const float4*>(out + (size_t)warp * D + c);
    float4 X = *reinterpret_cast<const float4*>(xs + (size_t)warp * D + c);
    float4 Bv = *reinterpret_cast<const float4*>(bias + c);
    float4 y;
    y.x = (A.x + ws * X.x) * inv + Bv.x;
    y.y = (A.y + ws * X.y) * inv + Bv.y;
    y.z = (A.z + ws * X.z) * inv + Bv.z;
    y.w = (A.w + ws * X.w) * inv + Bv.w;
    *reinterpret_cast<float4*>(out + (size_t)warp * D + c) = y;
}

// ---------------- misc ----------------
__global__ void compute_vdst(const float* __restrict__ Wd, const float* __restrict__ ad,
                             float* v) {
    int i = threadIdx.x;
    float sum = 0.f;
    for (int j = 0; j < D; j++) sum += Wd[i * D + j] * ad[j];
    v[i] = sum;
}

// ---------------- SAG readout (linearized) ----------------
__global__ void sag_prep(const float* __restrict__ x, const float* __restrict__ w_rel,
                         const float* __restrict__ w_root, const float* __restrict__ b_rel,
                         float* pRel, float* attn, int n) {
    int warp = (blockIdx.x * blockDim.x + threadIdx.x) >> 5;
    int lane = threadIdx.x & 31;
    if (warp >= n) return;
    int c = lane * 4;
    float4 xv = *reinterpret_cast<const float4*>(x + (size_t)warp * D + c);
    float4 wr = *reinterpret_cast<const float4*>(w_rel + c);
    float4 wo = *reinterpret_cast<const float4*>(w_root + c);
    float pr = xv.x * wr.x + xv.y * wr.y + xv.z * wr.z + xv.w * wr.w;
    float po = xv.x * wo.x + xv.y * wo.y + xv.z * wo.z + xv.w * wo.w;
    pr = warp_sum(pr);
    po = warp_sum(po);
    if (lane == 0) {
        pRel[warp] = pr;
        attn[warp] = po + __ldg(b_rel);
    }
}

__global__ void sag_edge(const int* __restrict__ src, const int* __restrict__ dst,
                         const float* __restrict__ pRel, float* attn, int E) {
    int e = blockIdx.x * blockDim.x + threadIdx.x;
    if (e >= E) return;
    atomicAdd(&attn[dst[e]], pRel[src[e]]);
}

__global__ void batch_expsum(float* attn, const int* __restrict__ batch,
                             float* sB, int n) {
    int i = blockIdx.x * blockDim.x + threadIdx.x;
    if (i >= n) return;
    float w = __expf(attn[i]);
    attn[i] = w;
    atomicAdd(&sB[batch[i]], w);
}

__global__ void emb_agg(const float* __restrict__ x, const float* __restrict__ attn,
                        const int* __restrict__ batch, const float* __restrict__ sB,
                        float* emb, int n) {
    int warp = (blockIdx.x * blockDim.x + threadIdx.x) >> 5;
    int lane = threadIdx.x & 31;
    if (warp >= n) return;
    int g = batch[warp];
    float coef = attn[warp] / (sB[g] + 1e-16f);
    int c = lane * 4;
    float4 xv = *reinterpret_cast<const float4*>(x + (size_t)warp * D + c);
    redAdd4(emb + (size_t)g * D + c, coef * xv.x, coef * xv.y, coef * xv.z, coef * xv.w);
}

// ---------------- host orchestration ----------------
extern "C" void kernel_launch(void* const* d_in, const int* in_sizes, int n_in,
                              void* d_out, int out_size) {
    const float* h_x        = (const float*)d_in[0];
    const float* t_x        = (const float*)d_in[1];
    const float* W_gat      = (const float*)d_in[2];
    const float* a_src_gat  = (const float*)d_in[3];
    const float* a_dst_gat  = (const float*)d_in[4];
    const float* b_gat      = (const float*)d_in[5];
    const float* ln_g       = (const float*)d_in[6];
    const float* ln_b       = (const float*)d_in[7];
    const float* W_intra    = (const float*)d_in[8];
    const float* a_src_in   = (const float*)d_in[9];
    const float* a_dst_in   = (const float*)d_in[10];
    const float* b_intra    = (const float*)d_in[11];
    const float* W_int_src  = (const float*)d_in[12];
    const float* W_int_dst  = (const float*)d_in[13];
    const float* a_src_it   = (const float*)d_in[14];
    const float* a_dst_it   = (const float*)d_in[15];
    const float* b_inter    = (const float*)d_in[16];
    const float* W_reduce   = (const float*)d_in[17];
    const float* b_reduce   = (const float*)d_in[18];
    const float* w_rel      = (const float*)d_in[19];
    const float* b_rel      = (const float*)d_in[20];
    const float* w_root     = (const float*)d_in[21];
    const int*   h_ei       = (const int*)d_in[22];
    const int*   t_ei       = (const int*)d_in[23];
    const int*   b_ei       = (const int*)d_in[24];
    const int*   h_batch    = (const int*)d_in[25];
    const int*   t_batch    = (const int*)d_in[26];
    (void)n_in;

    const int N = in_sizes[0] / 64;
    const int E = in_sizes[22] / 2;
    const long long B = ((long long)out_size - 6LL * N * D) / (2 * D);

    float* out = (float*)d_out;
    const size_t NT = (size_t)N * D, BT = (size_t)B * D;
    float* h_fused = out;
    float* t_fused = out + NT;
    float* h_emb   = out + 2 * NT;
    float* t_emb   = h_emb + BT;
    float* h_intra = t_emb + BT;
    float* t_intra = h_intra + NT;
    float* h_inter = t_intra + NT;
    float* t_inter = h_inter + NT;

    float *xh, *xt, *tmp, *acc, *alS, *alD, *s, *vdst, *sB;
    cudaGetSymbolAddress((void**)&xh,   g_xh);
    cudaGetSymbolAddress((void**)&xt,   g_xt);
    cudaGetSymbolAddress((void**)&tmp,  g_tmp);
    cudaGetSymbolAddress((void**)&acc,  g_acc);
    cudaGetSymbolAddress((void**)&alS,  g_alS);
    cudaGetSymbolAddress((void**)&alD,  g_alD);
    cudaGetSymbolAddress((void**)&s,    g_s);
    cudaGetSymbolAddress((void**)&vdst, g_vdst);
    cudaGetSymbolAddress((void**)&sB,   g_sB);

    const int TB = 256;
    const int nbNodeW = (N + 7) / 8;
    const int nbEdgeW = (E + 7) / 8;
    const int nbNodeT = (N + TB - 1) / TB;
    const int nbEdgeT = (E + TB - 1) / TB;
    const int nbGemm  = (N + 127) / 128;

    const int* h_src = h_ei;       const int* h_dst = h_ei + E;
    const int* t_src = t_ei;       const int* t_dst = t_ei + E;
    const int* b_src = b_ei;       const int* b_dst = b_ei + E;

    // ===== Stage 1: feature GAT + LN + ELU =====
    {
        const float* xin[2] = { h_x, t_x };
        const int* esrc[2]  = { h_src, t_src };
        const int* edst[2]  = { h_dst, t_dst };
        float* xout[2]      = { xh, xt };
        for (int g2 = 0; g2 < 2; g2++) {
            gemm_bf3<64><<<nbGemm, TB>>>(xin[g2], nullptr, W_gat, nullptr, tmp, N);
            cudaMemsetAsync(acc, 0, NT * sizeof(float));
            node_prep2<<<nbNodeW, TB>>>(tmp, a_src_gat, a_dst_gat, alS, alD, s, N);
            edge_agg2<<<nbEdgeW, TB>>>(esrc[g2], edst[g2], alS, alD, s, tmp, acc, E);
            fin_stage1<<<nbNodeW, TB>>>(acc, tmp, alS, alD, s, b_gat, ln_g, ln_b, xout[g2], N);
        }
    }

    // ===== Stage 2: intra GAT =====
    {
        const float* xin[2] = { xh, xt };
        const int* esrc[2]  = { h_src, t_src };
        const int* edst[2]  = { h_dst, t_dst };
        float* oreg[2]      = { h_intra, t_intra };
        for (int g2 = 0; g2 < 2; g2++) {
            gemm_bf3<128><<<nbGemm, TB>>>(xin[g2], nullptr, W_intra, nullptr, tmp, N);
            cudaMemsetAsync(oreg[g2], 0, NT * sizeof(float));
            node_prep1<<<nbNodeW, TB>>>(tmp, a_src_in, tmp, a_dst_in, alS, alD, s, N);
            edge_agg1<<<nbEdgeW, TB>>>(esrc[g2], edst[g2], alS, alD, s, tmp, oreg[g2], E);
            fin1<<<nbNodeW, TB>>>(oreg[g2], tmp, alS, alD, s, b_intra, 1, N);
        }
    }

    // ===== Stage 3: inter (bipartite) GAT =====
    compute_vdst<<<1, 128>>>(W_int_dst, a_dst_it, vdst);
    {
        gemm_bf3<128><<<nbGemm, TB>>>(xh, nullptr, W_int_src, nullptr, tmp, N);
        cudaMemsetAsync(t_inter, 0, NT * sizeof(float));
        node_prep1<<<nbNodeW, TB>>>(tmp, a_src_it, xt, vdst, alS, alD, s, N);
        edge_agg1<<<nbEdgeW, TB>>>(b_src, b_dst, alS, alD, s, tmp, t_inter, E);
        fin1<<<nbNodeW, TB>>>(t_inter, tmp, alS, alD, s, b_inter, 0, N);
    }
    {
        gemm_bf3<128><<<nbGemm, TB>>>(xt, nullptr, W_int_src, nullptr, tmp, N);
        cudaMemsetAsync(h_inter, 0, NT * sizeof(float));
        node_prep1<<<nbNodeW, TB>>>(tmp, a_src_it, xh, vdst, alS, alD, s, N);
        edge_agg1<<<nbEdgeW, TB>>>(b_dst, b_src, alS, alD, s, tmp, h_inter, E);
        fin1<<<nbNodeW, TB>>>(h_inter, tmp, alS, alD, s, b_inter, 0, N);
    }

    // ===== Stage 4: fused = [intra | inter] @ W_reduce + b_reduce (K=256) =====
    gemm_bf3<256><<<nbGemm, TB>>>(h_intra, h_inter, W_reduce, b_reduce, h_fused, N);
    gemm_bf3<256><<<nbGemm, TB>>>(t_intra, t_inter, W_reduce, b_reduce, t_fused, N);

    // ===== Stage 5: SAG readout (linearized) =====
    {
        const float* x[2]   = { h_fused, t_fused };
        const int* esrc[2]  = { h_src, t_src };
        const int* edst[2]  = { h_dst, t_dst };
        const int* batch[2] = { h_batch, t_batch };
        float* emb[2]       = { h_emb, t_emb };
        for (int g2 = 0; g2 < 2; g2++) {
            sag_prep<<<nbNodeW, TB>>>(x[g2], w_rel, w_root, b_rel, alS, alD, N);
            sag_edge<<<nbEdgeT, TB>>>(esrc[g2], edst[g2], alS, alD, E);
            cudaMemsetAsync(sB, 0, B * sizeof(float));
            batch_expsum<<<nbNodeT, TB>>>(alD, batch[g2], sB, N);
            cudaMemsetAsync(emb[g2], 0, BT * sizeof(float));
            emb_agg<<<nbNodeW, TB>>>(x[g2], alD, batch[g2], sB, emb[g2], N);
        }
    }
}